// round 8
// baseline (speedup 1.0000x reference)
#include <cuda_runtime.h>
#include <cstdint>

#define N_NODES 50000
#define N_EDGES 800000
#define ED 54
#define HID 64

// ---------------- scratch (device globals: allocation-free rule) ----------------
__device__ float g_agg[N_NODES * HID];   // layer-1 aggregation, 12.8 MB
__device__ float g_p[N_NODES * 56];      // p[0..53], q at [54], pad to 56
__device__ int   g_ei[2 * N_EDGES];      // normalized int32 indices
__device__ int   g_idx_is64;             // dtype flag

__device__ __forceinline__ uint32_t f2tf32(float f) {
    uint32_t r;
    asm("cvt.rna.tf32.f32 %0, %1;" : "=r"(r) : "f"(f));
    return r;
}

// ---------------- K0a: detect edge_index dtype ----------------
__global__ void k0a_detect(const int* __restrict__ ei_raw) {
    int lane = threadIdx.x;
    int nz = 0;
    #pragma unroll
    for (int r = 0; r < 2; r++) {
        int i = lane + r * 32;
        if (ei_raw[(2 * i * 9973 % (2 * N_EDGES)) | 1] != 0) nz = 1;
    }
    #pragma unroll
    for (int off = 16; off; off >>= 1) nz |= __shfl_down_sync(0xffffffffu, nz, off);
    if (lane == 0) g_idx_is64 = (nz == 0);
}

// ---------------- K0b: normalize indices (clamped) + zero g_agg ----------------
__global__ void k0b_convert_zero(const void* __restrict__ ei_raw) {
    int i = blockIdx.x * blockDim.x + threadIdx.x;   // 6250*256 = 1.6M exactly
    long long v;
    if (g_idx_is64) v = ((const long long*)ei_raw)[i];
    else            v = ((const int*)ei_raw)[i];
    if (v < 0) v = 0;
    if (v >= N_NODES) v = N_NODES - 1;
    g_ei[i] = (int)v;
    if (i < 800000) {                                 // 800000 float4s = 12.8MB
        float4 z = {0.f, 0.f, 0.f, 0.f};
        reinterpret_cast<float4*>(g_agg)[i] = z;
    }
}

// ---------------- K1: layer-1 edge GEMM via mma.sync tf32 + scatter ----------------
// Per 128-edge tile:  msgs[e,o] = sum_i x_i[e] * (A_raw[e,:] @ B_i[:,o])
//   A_raw[e,k] = ea[e,k] (k<54) | 1 (k==54) | 0 (k==55)   -- staged ONCE
//   B_i[k,o]   = w_e1[k, i*64+o] | b_e1[i*64+o] | 0       -- staged per slice i
// x_i folded into A-fragments at load (row-wise scale, exact).
// 4 warps; warp owns m=32 edges (mi=2 m16-tiles) x n=64; B frags shared across mi.
#define SA_STRIDE 136   // banks (8k+e)%32 -> conflict-free staging + frag loads
#define SB_STRIDE 72    // banks (8k+o)%32 -> conflict-free

__global__ __launch_bounds__(128, 4) void k1_mma(
    const float* __restrict__ x, const float* __restrict__ ea,
    const float* __restrict__ w_e1, const float* __restrict__ b_e1)
{
    __shared__ float    sA[56 * SA_STRIDE];   // 30464 B raw floats [k][e]
    __shared__ uint32_t sB[56 * SB_STRIDE];   // 16128 B tf32 bits  [k][o]
    __shared__ float    sXj[4 * 128];         // 2048 B [i][e]
    __shared__ int      sDst[128];            // 512 B          (total 49152 = 48KB)

    const int tid  = threadIdx.x;
    const int wid  = tid >> 5;
    const int lane = tid & 31;
    const int g    = lane >> 2;     // 0..7
    const int tg   = lane & 3;      // 0..3
    const int wb   = wid * 32;      // warp's edge base within tile
    const int e0   = blockIdx.x * 128;        // 6250*128 = 800000

    // ---- stage A (once): one edge column per thread ----
    {
        const float2* e2 = reinterpret_cast<const float2*>(ea + (size_t)(e0 + tid) * ED);
        #pragma unroll
        for (int j = 0; j < 27; j++) {
            float2 v = e2[j];
            sA[(2 * j) * SA_STRIDE + tid] = v.x;
            sA[(2 * j + 1) * SA_STRIDE + tid] = v.y;
        }
        sA[54 * SA_STRIDE + tid] = 1.0f;           // bias row
        sA[55 * SA_STRIDE + tid] = 0.0f;           // pad row

        int src = g_ei[e0 + tid];
        sDst[tid] = g_ei[N_EDGES + e0 + tid];
        float4 xv = *reinterpret_cast<const float4*>(x + (size_t)src * 4);
        sXj[0 * 128 + tid] = xv.x; sXj[1 * 128 + tid] = xv.y;
        sXj[2 * 128 + tid] = xv.z; sXj[3 * 128 + tid] = xv.w;
    }

    float acc[2][8][4];
    #pragma unroll
    for (int mi = 0; mi < 2; mi++)
        #pragma unroll
        for (int n = 0; n < 8; n++)
            #pragma unroll
            for (int c = 0; c < 4; c++) acc[mi][n][c] = 0.f;

    for (int i = 0; i < 4; i++) {
        __syncthreads();   // prior slice's mma reads done (i=0: A/x staging fence)
        // ---- stage B slice i ----
        for (int idx = tid; idx < 56 * 64; idx += 128) {
            int k = idx >> 6, o = idx & 63;
            float v = 0.f;
            if (k < 54)       v = w_e1[k * 256 + i * 64 + o];
            else if (k == 54) v = b_e1[i * 64 + o];
            sB[k * SB_STRIDE + o] = f2tf32(v);
        }
        __syncthreads();

        float xs[4];                    // per-mi row scales (edges wb+mi*16+{g, g+8})
        xs[0] = sXj[i * 128 + wb + g];
        xs[1] = sXj[i * 128 + wb + g + 8];
        xs[2] = sXj[i * 128 + wb + 16 + g];
        xs[3] = sXj[i * 128 + wb + 16 + g + 8];

        #pragma unroll
        for (int kb = 0; kb < 7; kb++) {
            const float* rA0 = sA + (kb * 8 + tg) * SA_STRIDE + wb;
            const float* rA4 = rA0 + 4 * SA_STRIDE;
            const uint32_t* rB0 = sB + (kb * 8 + tg) * SB_STRIDE + g;
            const uint32_t* rB4 = rB0 + 4 * SB_STRIDE;
            uint32_t afr[2][4];
            #pragma unroll
            for (int mi = 0; mi < 2; mi++) {
                int eb = mi * 16 + g;
                afr[mi][0] = f2tf32(rA0[eb] * xs[mi * 2]);
                afr[mi][1] = f2tf32(rA0[eb + 8] * xs[mi * 2 + 1]);
                afr[mi][2] = f2tf32(rA4[eb] * xs[mi * 2]);
                afr[mi][3] = f2tf32(rA4[eb + 8] * xs[mi * 2 + 1]);
            }
            #pragma unroll
            for (int n = 0; n < 8; n++) {
                uint32_t b0 = rB0[n * 8], b1 = rB4[n * 8];
                #pragma unroll
                for (int mi = 0; mi < 2; mi++) {
                    asm volatile(
                        "mma.sync.aligned.m16n8k8.row.col.f32.tf32.tf32.f32 "
                        "{%0,%1,%2,%3}, {%4,%5,%6,%7}, {%8,%9}, {%0,%1,%2,%3};"
                        : "+f"(acc[mi][n][0]), "+f"(acc[mi][n][1]),
                          "+f"(acc[mi][n][2]), "+f"(acc[mi][n][3])
                        : "r"(afr[mi][0]), "r"(afr[mi][1]), "r"(afr[mi][2]), "r"(afr[mi][3]),
                          "r"(b0), "r"(b1));
                }
            }
        }
    }

    // ---- epilogue: c0,c1 -> edge base+g; c2,c3 -> edge base+g+8; cols tg*2 + n*8 ----
    #pragma unroll
    for (int mi = 0; mi < 2; mi++) {
        int eb = wb + mi * 16 + g;
        int dA = sDst[eb], dB = sDst[eb + 8];
        float* pA = g_agg + (size_t)dA * HID + tg * 2;
        float* pB = g_agg + (size_t)dB * HID + tg * 2;
        #pragma unroll
        for (int n = 0; n < 8; n++) {
            asm volatile("red.global.add.v2.f32 [%0], {%1,%2};"
                         :: "l"(pA + n * 8), "f"(acc[mi][n][0]), "f"(acc[mi][n][1]) : "memory");
            asm volatile("red.global.add.v2.f32 [%0], {%1,%2};"
                         :: "l"(pB + n * 8), "f"(acc[mi][n][2]), "f"(acc[mi][n][3]) : "memory");
        }
    }
}

// ---------------- K2: node update; h = relu(agg + x@root1 + b1); emit p,q and out-init ----------------
__global__ __launch_bounds__(256) void k2_node(
    const float* __restrict__ x, const float* __restrict__ root1,
    const float* __restrict__ bias1, const float* __restrict__ w_e2,
    const float* __restrict__ b_e2, const float* __restrict__ root2,
    const float* __restrict__ bias2, float* __restrict__ out)
{
    __shared__ float sR1[256], sB1[64], sR2[64];
    __shared__ float sW2[55 * 65];      // row 54 = b_e2; stride 65 -> conflict-free
    __shared__ float sH[8][64];

    const int tid = threadIdx.x;
    for (int idx = tid; idx < 55 * 64; idx += 256) {
        int k = idx >> 6, o = idx & 63;
        sW2[k * 65 + o] = (k < 54) ? w_e2[k * 64 + o] : b_e2[o];
    }
    if (tid < 256) sR1[tid] = root1[tid];
    if (tid < 64) { sB1[tid] = bias1[tid]; sR2[tid] = root2[tid]; }
    __syncthreads();

    const int wid = tid >> 5, lane = tid & 31;
    const int n = blockIdx.x * 8 + wid;
    if (n >= N_NODES) return;

    const float* aggr = g_agg + (size_t)n * HID;
    float x0 = x[n * 4 + 0], x1 = x[n * 4 + 1], x2 = x[n * 4 + 2], x3 = x[n * 4 + 3];
    int l2 = lane + 32;
    float h0 = aggr[lane] + x0 * sR1[lane] + x1 * sR1[64 + lane]
             + x2 * sR1[128 + lane] + x3 * sR1[192 + lane] + sB1[lane];
    float h1 = aggr[l2] + x0 * sR1[l2] + x1 * sR1[64 + l2]
             + x2 * sR1[128 + l2] + x3 * sR1[192 + l2] + sB1[l2];
    h0 = fmaxf(h0, 0.f); h1 = fmaxf(h1, 0.f);
    sH[wid][lane] = h0; sH[wid][l2] = h1;
    __syncwarp();

    float* pn = g_p + (size_t)n * 56;
    {
        float acc = 0.f;
        #pragma unroll
        for (int o = 0; o < 64; o++) acc += sW2[lane * 65 + o] * sH[wid][o];
        pn[lane] = acc;
    }
    if (l2 < 55) {
        float acc = 0.f;
        #pragma unroll
        for (int o = 0; o < 64; o++) acc += sW2[l2 * 65 + o] * sH[wid][o];
        pn[l2] = acc;
    }
    float t = h0 * sR2[lane] + h1 * sR2[l2];
    #pragma unroll
    for (int off = 16; off; off >>= 1) t += __shfl_down_sync(0xffffffffu, t, off);
    if (lane == 0) out[n] = t + bias2[0];
}

// ---------------- K3: layer-2 edges: out[dst] += ea[e].p[src] + q[src] ----------------
__global__ __launch_bounds__(256) void k3_edge_layer2(
    const float* __restrict__ ea, float* __restrict__ out)
{
    const int tid = threadIdx.x, wid = tid >> 5, lane = tid & 31;
    const int e = blockIdx.x * 8 + wid;
    if (e >= N_EDGES) return;
    int src = g_ei[e], dst = g_ei[N_EDGES + e];
    float t = 0.f;
    if (lane < 27) {
        float2 av = reinterpret_cast<const float2*>(ea + (size_t)e * ED)[lane];
        float2 pv = reinterpret_cast<const float2*>(g_p + (size_t)src * 56)[lane];
        t = av.x * pv.x + av.y * pv.y;
    } else if (lane == 27) {
        t = g_p[(size_t)src * 56 + 54];          // q term (implicit ea=1)
    }
    #pragma unroll
    for (int off = 16; off; off >>= 1) t += __shfl_down_sync(0xffffffffu, t, off);
    if (lane == 0) atomicAdd(out + dst, t);
}

// ---------------- launch ----------------
extern "C" void kernel_launch(void* const* d_in, const int* in_sizes, int n_in,
                              void* d_out, int out_size) {
    const float* x     = (const float*)d_in[0];
    const void*  ei    = d_in[1];
    const float* ea    = (const float*)d_in[2];
    const float* w_e1  = (const float*)d_in[3];
    const float* b_e1  = (const float*)d_in[4];
    const float* root1 = (const float*)d_in[5];
    const float* bias1 = (const float*)d_in[6];
    const float* w_e2  = (const float*)d_in[7];
    const float* b_e2  = (const float*)d_in[8];
    const float* root2 = (const float*)d_in[9];
    const float* bias2 = (const float*)d_in[10];
    float* out = (float*)d_out;

    k0a_detect<<<1, 32>>>((const int*)ei);
    k0b_convert_zero<<<6250, 256>>>(ei);
    k1_mma<<<N_EDGES / 128, 128>>>(x, ea, w_e1, b_e1);
    k2_node<<<(N_NODES + 7) / 8, 256>>>(x, root1, bias1, w_e2, b_e2, root2, bias2, out);
    k3_edge_layer2<<<N_EDGES / 8, 256>>>(ea, out);
}

// round 9
// speedup vs baseline: 1.2819x; 1.2819x over previous
#include <cuda_runtime.h>
#include <cstdint>

#define N_NODES 50000
#define N_EDGES 800000
#define ED 54
#define HID 64

// ---------------- scratch (device globals: allocation-free rule) ----------------
__device__ float    g_agg[N_NODES * HID];   // layer-1 aggregation, 12.8 MB
__device__ float    g_p[N_NODES * 56];      // p[0..53], q at [54], pad to 56
__device__ int      g_ei[2 * N_EDGES];      // normalized int32 indices
__device__ uint32_t g_w1[4 * 56 * 64];      // w_e1/b_e1 pre-converted tf32, [slice][k][o]
__device__ int      g_idx_is64;             // dtype flag

__device__ __forceinline__ uint32_t f2tf32(float f) {
    uint32_t r;
    asm("cvt.rna.tf32.f32 %0, %1;" : "=r"(r) : "f"(f));
    return r;
}

// ---------------- K0a: detect edge_index dtype ----------------
__global__ void k0a_detect(const int* __restrict__ ei_raw) {
    int lane = threadIdx.x;
    int nz = 0;
    #pragma unroll
    for (int r = 0; r < 2; r++) {
        int i = lane + r * 32;
        if (ei_raw[(2 * i * 9973 % (2 * N_EDGES)) | 1] != 0) nz = 1;
    }
    #pragma unroll
    for (int off = 16; off; off >>= 1) nz |= __shfl_down_sync(0xffffffffu, nz, off);
    if (lane == 0) g_idx_is64 = (nz == 0);
}

// ---------------- K0b: normalize indices + zero g_agg + pre-convert w_e1 to tf32 ----------------
__global__ void k0b_convert_zero(const void* __restrict__ ei_raw,
                                 const float* __restrict__ w_e1,
                                 const float* __restrict__ b_e1) {
    int i = blockIdx.x * blockDim.x + threadIdx.x;   // 6250*256 = 1.6M exactly
    long long v;
    if (g_idx_is64) v = ((const long long*)ei_raw)[i];
    else            v = ((const int*)ei_raw)[i];
    if (v < 0) v = 0;
    if (v >= N_NODES) v = N_NODES - 1;
    g_ei[i] = (int)v;
    if (i < 800000) {                                 // 800000 float4s = 12.8MB
        float4 z = {0.f, 0.f, 0.f, 0.f};
        reinterpret_cast<float4*>(g_agg)[i] = z;
    }
    if (i < 4 * 56 * 64) {                            // tf32 weight prep
        int sl = i / 3584, r = i - sl * 3584;
        int k = r >> 6, o = r & 63;
        float w = 0.f;
        if (k < 54)       w = w_e1[k * 256 + sl * 64 + o];
        else if (k == 54) w = b_e1[sl * 64 + o];
        g_w1[i] = f2tf32(w);
    }
}

// ---------------- K1: layer-1 edge GEMM via mma.sync tf32 + scatter ----------------
// Per 128-edge tile: msgs[e,o] = sum_i x_i[e] * (A_raw[e,:] @ B_i[:,o])
//   A_raw held in REGISTERS (28 scalars/thread, loaded once from ea; k=54 -> 1.0, k=55 -> 0)
//   B_i copied from pre-converted g_w1 into smem per slice.
// 8 warps, warp owns m=16 edges x n=64 cols; K=56 per slice = 7 k8-steps.
#define SB_STRIDE 72    // banks (8k+o)%32 -> conflict-free frag loads

__global__ __launch_bounds__(256, 3) void k1_mma(
    const float* __restrict__ x, const float* __restrict__ ea)
{
    __shared__ uint32_t sB[56 * SB_STRIDE];   // 16128 B tf32 bits [k][o]

    const int tid  = threadIdx.x;
    const int wid  = tid >> 5;
    const int lane = tid & 31;
    const int g    = lane >> 2;     // 0..7
    const int tg   = lane & 3;      // 0..3
    const int wb   = wid * 16;      // warp's edge base within tile
    const int e0   = blockIdx.x * 128;        // 6250*128 = 800000

    // ---- per-thread edge metadata (2 edge rows: eA = wb+g, eB = wb+g+8) ----
    const int eA = e0 + wb + g, eB = e0 + wb + g + 8;
    const int srcA = g_ei[eA],          srcB = g_ei[eB];
    const int dstA = g_ei[N_EDGES + eA], dstB = g_ei[N_EDGES + eB];
    float4 xva = *reinterpret_cast<const float4*>(x + (size_t)srcA * 4);
    float4 xvb = *reinterpret_cast<const float4*>(x + (size_t)srcB * 4);
    float xA[4] = {xva.x, xva.y, xva.z, xva.w};
    float xB[4] = {xvb.x, xvb.y, xvb.z, xvb.w};

    // ---- raw A in registers: cols c1 = 8j+tg, c2 = 8j+tg+4 (j=0..6) ----
    const float* eaA = ea + (size_t)eA * ED;
    const float* eaB = ea + (size_t)eB * ED;
    float rA1[7], rA2[7], rB1[7], rB2[7];
    #pragma unroll
    for (int j = 0; j < 7; j++) { rA1[j] = eaA[8 * j + tg]; rB1[j] = eaB[8 * j + tg]; }
    #pragma unroll
    for (int j = 0; j < 6; j++) { rA2[j] = eaA[8 * j + tg + 4]; rB2[j] = eaB[8 * j + tg + 4]; }
    {   // j=6: col = 52+tg -> ea[52],ea[53], bias(1.0) at 54, pad(0) at 55
        if (tg < 2)      { rA2[6] = eaA[52 + tg]; rB2[6] = eaB[52 + tg]; }
        else if (tg == 2){ rA2[6] = 1.0f;         rB2[6] = 1.0f; }
        else             { rA2[6] = 0.0f;         rB2[6] = 0.0f; }
    }

    float acc[8][4];
    #pragma unroll
    for (int n = 0; n < 8; n++)
        #pragma unroll
        for (int c = 0; c < 4; c++) acc[n][c] = 0.f;

    #pragma unroll
    for (int i = 0; i < 4; i++) {
        __syncthreads();   // prior slice's mma reads of sB complete
        // ---- stage B slice i: plain u32 copy from pre-converted global ----
        #pragma unroll
        for (int it = 0; it < 14; it++) {               // 14*256 = 3584 = 56*64
            int idx = it * 256 + tid;
            sB[(idx >> 6) * SB_STRIDE + (idx & 63)] = g_w1[i * 3584 + idx];
        }
        __syncthreads();

        const float xa = xA[i], xb = xB[i];

        #pragma unroll
        for (int kb = 0; kb < 7; kb++) {
            uint32_t a0 = f2tf32(rA1[kb] * xa);
            uint32_t a1 = f2tf32(rB1[kb] * xb);
            uint32_t a2 = f2tf32(rA2[kb] * xa);
            uint32_t a3 = f2tf32(rB2[kb] * xb);
            const uint32_t* rB0 = sB + (kb * 8 + tg) * SB_STRIDE + g;
            const uint32_t* rB4 = rB0 + 4 * SB_STRIDE;
            #pragma unroll
            for (int n = 0; n < 8; n++) {
                uint32_t b0 = rB0[n * 8], b1 = rB4[n * 8];
                asm volatile(
                    "mma.sync.aligned.m16n8k8.row.col.f32.tf32.tf32.f32 "
                    "{%0,%1,%2,%3}, {%4,%5,%6,%7}, {%8,%9}, {%0,%1,%2,%3};"
                    : "+f"(acc[n][0]), "+f"(acc[n][1]), "+f"(acc[n][2]), "+f"(acc[n][3])
                    : "r"(a0), "r"(a1), "r"(a2), "r"(a3), "r"(b0), "r"(b1));
            }
        }
    }

    // ---- epilogue: c0,c1 -> edge eA; c2,c3 -> edge eB; cols tg*2 + n*8 ----
    float* pA = g_agg + (size_t)dstA * HID + tg * 2;
    float* pB = g_agg + (size_t)dstB * HID + tg * 2;
    #pragma unroll
    for (int n = 0; n < 8; n++) {
        asm volatile("red.global.add.v2.f32 [%0], {%1,%2};"
                     :: "l"(pA + n * 8), "f"(acc[n][0]), "f"(acc[n][1]) : "memory");
        asm volatile("red.global.add.v2.f32 [%0], {%1,%2};"
                     :: "l"(pB + n * 8), "f"(acc[n][2]), "f"(acc[n][3]) : "memory");
    }
}

// ---------------- K2: node update; h = relu(agg + x@root1 + b1); emit p,q and out-init ----------------
__global__ __launch_bounds__(256) void k2_node(
    const float* __restrict__ x, const float* __restrict__ root1,
    const float* __restrict__ bias1, const float* __restrict__ w_e2,
    const float* __restrict__ b_e2, const float* __restrict__ root2,
    const float* __restrict__ bias2, float* __restrict__ out)
{
    __shared__ float sR1[256], sB1[64], sR2[64];
    __shared__ float sW2[55 * 65];      // row 54 = b_e2; stride 65 -> conflict-free
    __shared__ float sH[8][64];

    const int tid = threadIdx.x;
    for (int idx = tid; idx < 55 * 64; idx += 256) {
        int k = idx >> 6, o = idx & 63;
        sW2[k * 65 + o] = (k < 54) ? w_e2[k * 64 + o] : b_e2[o];
    }
    if (tid < 256) sR1[tid] = root1[tid];
    if (tid < 64) { sB1[tid] = bias1[tid]; sR2[tid] = root2[tid]; }
    __syncthreads();

    const int wid = tid >> 5, lane = tid & 31;
    const int n = blockIdx.x * 8 + wid;
    if (n >= N_NODES) return;

    const float* aggr = g_agg + (size_t)n * HID;
    float x0 = x[n * 4 + 0], x1 = x[n * 4 + 1], x2 = x[n * 4 + 2], x3 = x[n * 4 + 3];
    int l2 = lane + 32;
    float h0 = aggr[lane] + x0 * sR1[lane] + x1 * sR1[64 + lane]
             + x2 * sR1[128 + lane] + x3 * sR1[192 + lane] + sB1[lane];
    float h1 = aggr[l2] + x0 * sR1[l2] + x1 * sR1[64 + l2]
             + x2 * sR1[128 + l2] + x3 * sR1[192 + l2] + sB1[l2];
    h0 = fmaxf(h0, 0.f); h1 = fmaxf(h1, 0.f);
    sH[wid][lane] = h0; sH[wid][l2] = h1;
    __syncwarp();

    float* pn = g_p + (size_t)n * 56;
    {
        float acc = 0.f;
        #pragma unroll
        for (int o = 0; o < 64; o++) acc += sW2[lane * 65 + o] * sH[wid][o];
        pn[lane] = acc;
    }
    if (l2 < 55) {
        float acc = 0.f;
        #pragma unroll
        for (int o = 0; o < 64; o++) acc += sW2[l2 * 65 + o] * sH[wid][o];
        pn[l2] = acc;
    }
    float t = h0 * sR2[lane] + h1 * sR2[l2];
    #pragma unroll
    for (int off = 16; off; off >>= 1) t += __shfl_down_sync(0xffffffffu, t, off);
    if (lane == 0) out[n] = t + bias2[0];
}

// ---------------- K3: layer-2 edges: out[dst] += ea[e].p[src] + q[src] ----------------
__global__ __launch_bounds__(256) void k3_edge_layer2(
    const float* __restrict__ ea, float* __restrict__ out)
{
    const int tid = threadIdx.x, wid = tid >> 5, lane = tid & 31;
    const int e = blockIdx.x * 8 + wid;
    if (e >= N_EDGES) return;
    int src = g_ei[e], dst = g_ei[N_EDGES + e];
    float t = 0.f;
    if (lane < 27) {
        float2 av = reinterpret_cast<const float2*>(ea + (size_t)e * ED)[lane];
        float2 pv = reinterpret_cast<const float2*>(g_p + (size_t)src * 56)[lane];
        t = av.x * pv.x + av.y * pv.y;
    } else if (lane == 27) {
        t = g_p[(size_t)src * 56 + 54];          // q term (implicit ea=1)
    }
    #pragma unroll
    for (int off = 16; off; off >>= 1) t += __shfl_down_sync(0xffffffffu, t, off);
    if (lane == 0) atomicAdd(out + dst, t);
}

// ---------------- launch ----------------
extern "C" void kernel_launch(void* const* d_in, const int* in_sizes, int n_in,
                              void* d_out, int out_size) {
    const float* x     = (const float*)d_in[0];
    const void*  ei    = d_in[1];
    const float* ea    = (const float*)d_in[2];
    const float* w_e1  = (const float*)d_in[3];
    const float* b_e1  = (const float*)d_in[4];
    const float* root1 = (const float*)d_in[5];
    const float* bias1 = (const float*)d_in[6];
    const float* w_e2  = (const float*)d_in[7];
    const float* b_e2  = (const float*)d_in[8];
    const float* root2 = (const float*)d_in[9];
    const float* bias2 = (const float*)d_in[10];
    float* out = (float*)d_out;

    k0a_detect<<<1, 32>>>((const int*)ei);
    k0b_convert_zero<<<6250, 256>>>(ei, w_e1, b_e1);
    k1_mma<<<N_EDGES / 128, 256>>>(x, ea);
    k2_node<<<(N_NODES + 7) / 8, 256>>>(x, root1, bias1, w_e2, b_e2, root2, bias2, out);
    k3_edge_layer2<<<N_EDGES / 8, 256>>>(ea, out);
}

// round 10
// speedup vs baseline: 1.2859x; 1.0031x over previous
#include <cuda_runtime.h>
#include <cstdint>

#define N_NODES 50000
#define N_EDGES 800000
#define ED 54
#define HID 64

// ---------------- scratch (device globals: allocation-free rule) ----------------
__device__ float    g_agg[N_NODES * HID];   // layer-1 aggregation, 12.8 MB
__device__ float    g_p[N_NODES * 56];      // p[0..53], q at [54], pad to 56
__device__ int      g_ei[2 * N_EDGES];      // normalized int32 indices
__device__ uint32_t g_w1[4 * 56 * 64];      // w_e1/b_e1 pre-converted tf32, [slice][k][o]
__device__ int      g_idx_is64;             // dtype flag

__device__ __forceinline__ uint32_t f2tf32(float f) {
    uint32_t r;
    asm("cvt.rna.tf32.f32 %0, %1;" : "=r"(r) : "f"(f));
    return r;
}

// ---------------- K0a: detect edge_index dtype ----------------
__global__ void k0a_detect(const int* __restrict__ ei_raw) {
    int lane = threadIdx.x;
    int nz = 0;
    #pragma unroll
    for (int r = 0; r < 2; r++) {
        int i = lane + r * 32;
        if (ei_raw[(2 * i * 9973 % (2 * N_EDGES)) | 1] != 0) nz = 1;
    }
    #pragma unroll
    for (int off = 16; off; off >>= 1) nz |= __shfl_down_sync(0xffffffffu, nz, off);
    if (lane == 0) g_idx_is64 = (nz == 0);
}

// ---------------- K0b: normalize indices + zero g_agg + pre-convert w_e1 to tf32 ----------------
__global__ void k0b_convert_zero(const void* __restrict__ ei_raw,
                                 const float* __restrict__ w_e1,
                                 const float* __restrict__ b_e1) {
    int i = blockIdx.x * blockDim.x + threadIdx.x;   // 6250*256 = 1.6M exactly
    long long v;
    if (g_idx_is64) v = ((const long long*)ei_raw)[i];
    else            v = ((const int*)ei_raw)[i];
    if (v < 0) v = 0;
    if (v >= N_NODES) v = N_NODES - 1;
    g_ei[i] = (int)v;
    if (i < 800000) {                                 // 800000 float4s = 12.8MB
        float4 z = {0.f, 0.f, 0.f, 0.f};
        reinterpret_cast<float4*>(g_agg)[i] = z;
    }
    if (i < 4 * 56 * 64) {                            // tf32 weight prep
        int sl = i / 3584, r = i - sl * 3584;
        int k = r >> 6, o = r & 63;
        float w = 0.f;
        if (k < 54)       w = w_e1[k * 256 + sl * 64 + o];
        else if (k == 54) w = b_e1[sl * 64 + o];
        g_w1[i] = f2tf32(w);
    }
}

// ---------------- K1: layer-1 edge GEMM via mma.sync tf32 + scatter ----------------
// Per 128-edge tile: msgs[e,o] = sum_i x_i[e] * (A_raw[e,:] @ B_i[:,o])
//   A_raw held in REGISTERS (28 scalars/thread, loaded once from ea; k=54 -> 1.0, k=55 -> 0)
//   B_i copied from pre-converted g_w1 into smem per slice.
// 8 warps, warp owns m=16 edges x n=64 cols; K=56 per slice = 7 k8-steps.
#define SB_STRIDE 72    // banks (8k+o)%32 -> conflict-free frag loads

__global__ __launch_bounds__(256, 3) void k1_mma(
    const float* __restrict__ x, const float* __restrict__ ea)
{
    __shared__ uint32_t sB[56 * SB_STRIDE];   // 16128 B tf32 bits [k][o]

    const int tid  = threadIdx.x;
    const int wid  = tid >> 5;
    const int lane = tid & 31;
    const int g    = lane >> 2;     // 0..7
    const int tg   = lane & 3;      // 0..3
    const int wb   = wid * 16;      // warp's edge base within tile
    const int e0   = blockIdx.x * 128;        // 6250*128 = 800000

    // ---- per-thread edge metadata (2 edge rows: eA = wb+g, eB = wb+g+8) ----
    const int eA = e0 + wb + g, eB = e0 + wb + g + 8;
    const int srcA = g_ei[eA],          srcB = g_ei[eB];
    const int dstA = g_ei[N_EDGES + eA], dstB = g_ei[N_EDGES + eB];
    float4 xva = *reinterpret_cast<const float4*>(x + (size_t)srcA * 4);
    float4 xvb = *reinterpret_cast<const float4*>(x + (size_t)srcB * 4);
    float xA[4] = {xva.x, xva.y, xva.z, xva.w};
    float xB[4] = {xvb.x, xvb.y, xvb.z, xvb.w};

    // ---- raw A in registers: cols c1 = 8j+tg, c2 = 8j+tg+4 (j=0..6) ----
    const float* eaA = ea + (size_t)eA * ED;
    const float* eaB = ea + (size_t)eB * ED;
    float rA1[7], rA2[7], rB1[7], rB2[7];
    #pragma unroll
    for (int j = 0; j < 7; j++) { rA1[j] = eaA[8 * j + tg]; rB1[j] = eaB[8 * j + tg]; }
    #pragma unroll
    for (int j = 0; j < 6; j++) { rA2[j] = eaA[8 * j + tg + 4]; rB2[j] = eaB[8 * j + tg + 4]; }
    {   // j=6: col = 52+tg -> ea[52],ea[53], bias(1.0) at 54, pad(0) at 55
        if (tg < 2)      { rA2[6] = eaA[52 + tg]; rB2[6] = eaB[52 + tg]; }
        else if (tg == 2){ rA2[6] = 1.0f;         rB2[6] = 1.0f; }
        else             { rA2[6] = 0.0f;         rB2[6] = 0.0f; }
    }

    float acc[8][4];
    #pragma unroll
    for (int n = 0; n < 8; n++)
        #pragma unroll
        for (int c = 0; c < 4; c++) acc[n][c] = 0.f;

    #pragma unroll
    for (int i = 0; i < 4; i++) {
        __syncthreads();   // prior slice's mma reads of sB complete
        // ---- stage B slice i: plain u32 copy from pre-converted global ----
        #pragma unroll
        for (int it = 0; it < 14; it++) {               // 14*256 = 3584 = 56*64
            int idx = it * 256 + tid;
            sB[(idx >> 6) * SB_STRIDE + (idx & 63)] = g_w1[i * 3584 + idx];
        }
        __syncthreads();

        const float xa = xA[i], xb = xB[i];

        #pragma unroll
        for (int kb = 0; kb < 7; kb++) {
            uint32_t a0 = f2tf32(rA1[kb] * xa);
            uint32_t a1 = f2tf32(rB1[kb] * xb);
            uint32_t a2 = f2tf32(rA2[kb] * xa);
            uint32_t a3 = f2tf32(rB2[kb] * xb);
            const uint32_t* rB0 = sB + (kb * 8 + tg) * SB_STRIDE + g;
            const uint32_t* rB4 = rB0 + 4 * SB_STRIDE;
            #pragma unroll
            for (int n = 0; n < 8; n++) {
                uint32_t b0 = rB0[n * 8], b1 = rB4[n * 8];
                asm volatile(
                    "mma.sync.aligned.m16n8k8.row.col.f32.tf32.tf32.f32 "
                    "{%0,%1,%2,%3}, {%4,%5,%6,%7}, {%8,%9}, {%0,%1,%2,%3};"
                    : "+f"(acc[n][0]), "+f"(acc[n][1]), "+f"(acc[n][2]), "+f"(acc[n][3])
                    : "r"(a0), "r"(a1), "r"(a2), "r"(a3), "r"(b0), "r"(b1));
            }
        }
    }

    // ---- epilogue: c0,c1 -> edge eA; c2,c3 -> edge eB; cols tg*2 + n*8 ----
    float* pA = g_agg + (size_t)dstA * HID + tg * 2;
    float* pB = g_agg + (size_t)dstB * HID + tg * 2;
    #pragma unroll
    for (int n = 0; n < 8; n++) {
        asm volatile("red.global.add.v2.f32 [%0], {%1,%2};"
                     :: "l"(pA + n * 8), "f"(acc[n][0]), "f"(acc[n][1]) : "memory");
        asm volatile("red.global.add.v2.f32 [%0], {%1,%2};"
                     :: "l"(pB + n * 8), "f"(acc[n][2]), "f"(acc[n][3]) : "memory");
    }
}

// ---------------- K2: node update; h = relu(agg + x@root1 + b1); emit p,q and out-init ----------------
__global__ __launch_bounds__(256) void k2_node(
    const float* __restrict__ x, const float* __restrict__ root1,
    const float* __restrict__ bias1, const float* __restrict__ w_e2,
    const float* __restrict__ b_e2, const float* __restrict__ root2,
    const float* __restrict__ bias2, float* __restrict__ out)
{
    __shared__ float sR1[256], sB1[64], sR2[64];
    __shared__ float sW2[55 * 65];      // row 54 = b_e2; stride 65 -> conflict-free
    __shared__ float sH[8][64];

    const int tid = threadIdx.x;
    for (int idx = tid; idx < 55 * 64; idx += 256) {
        int k = idx >> 6, o = idx & 63;
        sW2[k * 65 + o] = (k < 54) ? w_e2[k * 64 + o] : b_e2[o];
    }
    if (tid < 256) sR1[tid] = root1[tid];
    if (tid < 64) { sB1[tid] = bias1[tid]; sR2[tid] = root2[tid]; }
    __syncthreads();

    const int wid = tid >> 5, lane = tid & 31;
    const int n = blockIdx.x * 8 + wid;
    if (n >= N_NODES) return;

    const float* aggr = g_agg + (size_t)n * HID;
    float x0 = x[n * 4 + 0], x1 = x[n * 4 + 1], x2 = x[n * 4 + 2], x3 = x[n * 4 + 3];
    int l2 = lane + 32;
    float h0 = aggr[lane] + x0 * sR1[lane] + x1 * sR1[64 + lane]
             + x2 * sR1[128 + lane] + x3 * sR1[192 + lane] + sB1[lane];
    float h1 = aggr[l2] + x0 * sR1[l2] + x1 * sR1[64 + l2]
             + x2 * sR1[128 + l2] + x3 * sR1[192 + l2] + sB1[l2];
    h0 = fmaxf(h0, 0.f); h1 = fmaxf(h1, 0.f);
    sH[wid][lane] = h0; sH[wid][l2] = h1;
    __syncwarp();

    float* pn = g_p + (size_t)n * 56;
    {
        float acc = 0.f;
        #pragma unroll
        for (int o = 0; o < 64; o++) acc += sW2[lane * 65 + o] * sH[wid][o];
        pn[lane] = acc;
    }
    if (l2 < 55) {
        float acc = 0.f;
        #pragma unroll
        for (int o = 0; o < 64; o++) acc += sW2[l2 * 65 + o] * sH[wid][o];
        pn[l2] = acc;
    }
    float t = h0 * sR2[lane] + h1 * sR2[l2];
    #pragma unroll
    for (int off = 16; off; off >>= 1) t += __shfl_down_sync(0xffffffffu, t, off);
    if (lane == 0) out[n] = t + bias2[0];
}

// ---------------- K3: layer-2 edges: out[dst] += ea[e].p[src] + q[src] ----------------
__global__ __launch_bounds__(256) void k3_edge_layer2(
    const float* __restrict__ ea, float* __restrict__ out)
{
    const int tid = threadIdx.x, wid = tid >> 5, lane = tid & 31;
    const int e = blockIdx.x * 8 + wid;
    if (e >= N_EDGES) return;
    int src = g_ei[e], dst = g_ei[N_EDGES + e];
    float t = 0.f;
    if (lane < 27) {
        float2 av = reinterpret_cast<const float2*>(ea + (size_t)e * ED)[lane];
        float2 pv = reinterpret_cast<const float2*>(g_p + (size_t)src * 56)[lane];
        t = av.x * pv.x + av.y * pv.y;
    } else if (lane == 27) {
        t = g_p[(size_t)src * 56 + 54];          // q term (implicit ea=1)
    }
    #pragma unroll
    for (int off = 16; off; off >>= 1) t += __shfl_down_sync(0xffffffffu, t, off);
    if (lane == 0) atomicAdd(out + dst, t);
}

// ---------------- launch ----------------
extern "C" void kernel_launch(void* const* d_in, const int* in_sizes, int n_in,
                              void* d_out, int out_size) {
    const float* x     = (const float*)d_in[0];
    const void*  ei    = d_in[1];
    const float* ea    = (const float*)d_in[2];
    const float* w_e1  = (const float*)d_in[3];
    const float* b_e1  = (const float*)d_in[4];
    const float* root1 = (const float*)d_in[5];
    const float* bias1 = (const float*)d_in[6];
    const float* w_e2  = (const float*)d_in[7];
    const float* b_e2  = (const float*)d_in[8];
    const float* root2 = (const float*)d_in[9];
    const float* bias2 = (const float*)d_in[10];
    float* out = (float*)d_out;

    k0a_detect<<<1, 32>>>((const int*)ei);
    k0b_convert_zero<<<6250, 256>>>(ei, w_e1, b_e1);
    k1_mma<<<N_EDGES / 128, 256>>>(x, ea);
    k2_node<<<(N_NODES + 7) / 8, 256>>>(x, root1, bias1, w_e2, b_e2, root2, bias2, out);
    k3_edge_layer2<<<N_EDGES / 8, 256>>>(ea, out);
}

// round 11
// speedup vs baseline: 1.4259x; 1.1089x over previous
#include <cuda_runtime.h>
#include <cstdint>

#define N_NODES 50000
#define N_EDGES 800000
#define ED 54
#define HID 64

// ---------------- scratch (device globals: allocation-free rule) ----------------
__device__ float    g_agg[N_NODES * HID];   // layer-1 aggregation, 12.8 MB
__device__ float    g_p[N_NODES * 56];      // p[0..53], q at [54], pad to 56
__device__ int      g_ei[2 * N_EDGES];      // normalized int32 indices
__device__ uint2    g_w1[4 * 1856];         // tf32 B-frag pairs, [slice][o][kb][tg], stride 29
__device__ int      g_idx_is64;             // dtype flag

__device__ __forceinline__ uint32_t f2tf32(float f) {
    uint32_t r;
    asm("cvt.rna.tf32.f32 %0, %1;" : "=r"(r) : "f"(f));
    return r;
}

// ---------------- K0a: detect edge_index dtype ----------------
__global__ void k0a_detect(const int* __restrict__ ei_raw) {
    int lane = threadIdx.x;
    int nz = 0;
    #pragma unroll
    for (int r = 0; r < 2; r++) {
        int i = lane + r * 32;
        if (ei_raw[(2 * i * 9973 % (2 * N_EDGES)) | 1] != 0) nz = 1;
    }
    #pragma unroll
    for (int off = 16; off; off >>= 1) nz |= __shfl_down_sync(0xffffffffu, nz, off);
    if (lane == 0) g_idx_is64 = (nz == 0);
}

// ---------------- K0b: normalize indices + zero g_agg + pack w_e1 tf32 pairs ----------------
__global__ void k0b_convert_zero(const void* __restrict__ ei_raw,
                                 const float* __restrict__ w_e1,
                                 const float* __restrict__ b_e1) {
    int i = blockIdx.x * blockDim.x + threadIdx.x;   // 6250*256 = 1.6M exactly
    long long v;
    if (g_idx_is64) v = ((const long long*)ei_raw)[i];
    else            v = ((const int*)ei_raw)[i];
    if (v < 0) v = 0;
    if (v >= N_NODES) v = N_NODES - 1;
    g_ei[i] = (int)v;
    if (i < 800000) {                                 // 800000 float4s = 12.8MB
        float4 z = {0.f, 0.f, 0.f, 0.f};
        reinterpret_cast<float4*>(g_agg)[i] = z;
    }
    if (i < 4 * 1856) {                               // tf32 B-frag pair prep
        int sl = i / 1856, r = i - sl * 1856;
        int o = r / 29, rr = r - o * 29;
        uint2 val = {0u, 0u};
        if (rr < 28) {
            int kb = rr >> 2, tg = rr & 3;
            int k0 = kb * 8 + tg, k1 = k0 + 4;
            int c = sl * 64 + o;
            float w0 = (k0 < 54) ? w_e1[k0 * 256 + c] : ((k0 == 54) ? b_e1[c] : 0.f);
            float w1 = (k1 < 54) ? w_e1[k1 * 256 + c] : ((k1 == 54) ? b_e1[c] : 0.f);
            val.x = f2tf32(w0); val.y = f2tf32(w1);
        }
        g_w1[i] = val;
    }
}

// ---------------- K1: layer-1 edge GEMM via mma.sync tf32 + scatter ----------------
// Per 128-edge tile: msgs[e,o] = sum_i x_i[e] * (A_raw[e,:] @ B_i[:,o])
//   A_raw held in REGISTERS (28 scalars/thread; k=54 -> 1.0, k=55 -> 0)
//   B_i frag-pairs copied from pre-packed g_w1 into smem per slice (uint2).
// 8 warps, warp owns m=16 edges x n=64 cols; K=56 per slice = 7 k8-steps.
__global__ __launch_bounds__(256, 3) void k1_mma(
    const float* __restrict__ x, const float* __restrict__ ea)
{
    __shared__ uint2 sB[1856];   // 14848 B: [o][kb][tg] stride 29

    const int tid  = threadIdx.x;
    const int wid  = tid >> 5;
    const int lane = tid & 31;
    const int g    = lane >> 2;     // 0..7
    const int tg   = lane & 3;      // 0..3
    const int wb   = wid * 16;      // warp's edge base within tile
    const int e0   = blockIdx.x * 128;        // 6250*128 = 800000

    // ---- per-thread edge metadata (2 edge rows: eA = wb+g, eB = wb+g+8) ----
    const int eA = e0 + wb + g, eB = e0 + wb + g + 8;
    const int srcA = g_ei[eA],          srcB = g_ei[eB];
    const int dstA = g_ei[N_EDGES + eA], dstB = g_ei[N_EDGES + eB];
    float4 xva = *reinterpret_cast<const float4*>(x + (size_t)srcA * 4);
    float4 xvb = *reinterpret_cast<const float4*>(x + (size_t)srcB * 4);
    float xA[4] = {xva.x, xva.y, xva.z, xva.w};
    float xB[4] = {xvb.x, xvb.y, xvb.z, xvb.w};

    // ---- raw A in registers: cols c1 = 8j+tg, c2 = 8j+tg+4 (j=0..6) ----
    const float* eaA = ea + (size_t)eA * ED;
    const float* eaB = ea + (size_t)eB * ED;
    float rA1[7], rA2[7], rB1[7], rB2[7];
    #pragma unroll
    for (int j = 0; j < 7; j++) { rA1[j] = eaA[8 * j + tg]; rB1[j] = eaB[8 * j + tg]; }
    #pragma unroll
    for (int j = 0; j < 6; j++) { rA2[j] = eaA[8 * j + tg + 4]; rB2[j] = eaB[8 * j + tg + 4]; }
    {   // j=6: col = 52+tg -> ea[52],ea[53], bias(1.0) at 54, pad(0) at 55
        if (tg < 2)      { rA2[6] = eaA[52 + tg]; rB2[6] = eaB[52 + tg]; }
        else if (tg == 2){ rA2[6] = 1.0f;         rB2[6] = 1.0f; }
        else             { rA2[6] = 0.0f;         rB2[6] = 0.0f; }
    }

    float acc[8][4];
    #pragma unroll
    for (int n = 0; n < 8; n++)
        #pragma unroll
        for (int c = 0; c < 4; c++) acc[n][c] = 0.f;

    #pragma unroll
    for (int i = 0; i < 4; i++) {
        __syncthreads();   // prior slice's mma reads of sB complete
        // ---- stage B slice i: plain uint2 copy from pre-packed global ----
        #pragma unroll
        for (int it = 0; it < 7; it++)                  // 7*256 = 1792
            sB[it * 256 + tid] = g_w1[i * 1856 + it * 256 + tid];
        if (tid < 64) sB[1792 + tid] = g_w1[i * 1856 + 1792 + tid];
        __syncthreads();

        const float xa = xA[i], xb = xB[i];

        #pragma unroll
        for (int kb = 0; kb < 7; kb++) {
            uint32_t a0 = f2tf32(rA1[kb] * xa);
            uint32_t a1 = f2tf32(rB1[kb] * xb);
            uint32_t a2 = f2tf32(rA2[kb] * xa);
            uint32_t a3 = f2tf32(rB2[kb] * xb);
            const uint2* bp = sB + g * 29 + kb * 4 + tg;
            #pragma unroll
            for (int n = 0; n < 8; n++) {
                uint2 b = bp[n * 8 * 29];
                asm volatile(
                    "mma.sync.aligned.m16n8k8.row.col.f32.tf32.tf32.f32 "
                    "{%0,%1,%2,%3}, {%4,%5,%6,%7}, {%8,%9}, {%0,%1,%2,%3};"
                    : "+f"(acc[n][0]), "+f"(acc[n][1]), "+f"(acc[n][2]), "+f"(acc[n][3])
                    : "r"(a0), "r"(a1), "r"(a2), "r"(a3), "r"(b.x), "r"(b.y));
            }
        }
    }

    // ---- epilogue: c0,c1 -> edge eA; c2,c3 -> edge eB; cols tg*2 + n*8 ----
    float* pA = g_agg + (size_t)dstA * HID + tg * 2;
    float* pB = g_agg + (size_t)dstB * HID + tg * 2;
    #pragma unroll
    for (int n = 0; n < 8; n++) {
        asm volatile("red.global.add.v2.f32 [%0], {%1,%2};"
                     :: "l"(pA + n * 8), "f"(acc[n][0]), "f"(acc[n][1]) : "memory");
        asm volatile("red.global.add.v2.f32 [%0], {%1,%2};"
                     :: "l"(pB + n * 8), "f"(acc[n][2]), "f"(acc[n][3]) : "memory");
    }
}

// ---------------- K2: node update, 2 nodes per warp ----------------
__global__ __launch_bounds__(256) void k2_node(
    const float* __restrict__ x, const float* __restrict__ root1,
    const float* __restrict__ bias1, const float* __restrict__ w_e2,
    const float* __restrict__ b_e2, const float* __restrict__ root2,
    const float* __restrict__ bias2, float* __restrict__ out)
{
    __shared__ float sR1[256], sB1[64], sR2[64];
    __shared__ float sW2[55 * 65];      // row 54 = b_e2; stride 65 -> conflict-free
    __shared__ float sH[16][64];

    const int tid = threadIdx.x;
    for (int idx = tid; idx < 55 * 64; idx += 256) {
        int k = idx >> 6, o = idx & 63;
        sW2[k * 65 + o] = (k < 54) ? w_e2[k * 64 + o] : b_e2[o];
    }
    if (tid < 256) sR1[tid] = root1[tid];
    if (tid < 64) { sB1[tid] = bias1[tid]; sR2[tid] = root2[tid]; }
    __syncthreads();

    const int wid = tid >> 5, lane = tid & 31;
    const int n1 = blockIdx.x * 16 + wid * 2;        // grid 3125 -> exactly 50000 nodes
    const int n2 = n1 + 1;
    const int l2 = lane + 32;

    const float* ag1 = g_agg + (size_t)n1 * HID;
    const float* ag2 = g_agg + (size_t)n2 * HID;
    float4 xv1 = *reinterpret_cast<const float4*>(x + (size_t)n1 * 4);
    float4 xv2 = *reinterpret_cast<const float4*>(x + (size_t)n2 * 4);

    float h1a = ag1[lane] + xv1.x * sR1[lane] + xv1.y * sR1[64 + lane]
              + xv1.z * sR1[128 + lane] + xv1.w * sR1[192 + lane] + sB1[lane];
    float h1b = ag1[l2] + xv1.x * sR1[l2] + xv1.y * sR1[64 + l2]
              + xv1.z * sR1[128 + l2] + xv1.w * sR1[192 + l2] + sB1[l2];
    float h2a = ag2[lane] + xv2.x * sR1[lane] + xv2.y * sR1[64 + lane]
              + xv2.z * sR1[128 + lane] + xv2.w * sR1[192 + lane] + sB1[lane];
    float h2b = ag2[l2] + xv2.x * sR1[l2] + xv2.y * sR1[64 + l2]
              + xv2.z * sR1[128 + l2] + xv2.w * sR1[192 + l2] + sB1[l2];
    h1a = fmaxf(h1a, 0.f); h1b = fmaxf(h1b, 0.f);
    h2a = fmaxf(h2a, 0.f); h2b = fmaxf(h2b, 0.f);
    sH[wid * 2][lane] = h1a; sH[wid * 2][l2] = h1b;
    sH[wid * 2 + 1][lane] = h2a; sH[wid * 2 + 1][l2] = h2b;
    __syncwarp();

    const float* hr1 = sH[wid * 2];
    const float* hr2 = sH[wid * 2 + 1];
    float* p1 = g_p + (size_t)n1 * 56;
    float* p2 = g_p + (size_t)n2 * 56;
    {
        float a1 = 0.f, a2 = 0.f;
        #pragma unroll
        for (int o = 0; o < 64; o++) {
            float w = sW2[lane * 65 + o];
            a1 += w * hr1[o]; a2 += w * hr2[o];
        }
        p1[lane] = a1; p2[lane] = a2;
    }
    if (l2 < 55) {
        float a1 = 0.f, a2 = 0.f;
        #pragma unroll
        for (int o = 0; o < 64; o++) {
            float w = sW2[l2 * 65 + o];
            a1 += w * hr1[o]; a2 += w * hr2[o];
        }
        p1[l2] = a1; p2[l2] = a2;
    }
    // out init = h @ root2 + bias2
    float t1 = h1a * sR2[lane] + h1b * sR2[l2];
    float t2 = h2a * sR2[lane] + h2b * sR2[l2];
    #pragma unroll
    for (int off = 16; off; off >>= 1) {
        t1 += __shfl_down_sync(0xffffffffu, t1, off);
        t2 += __shfl_down_sync(0xffffffffu, t2, off);
    }
    if (lane == 0) { out[n1] = t1 + bias2[0]; out[n2] = t2 + bias2[0]; }
}

// ---------------- K3: layer-2 edges, 4 edges per warp (8 lanes each) ----------------
__global__ __launch_bounds__(256) void k3_edge_layer2(
    const float* __restrict__ ea, float* __restrict__ out)
{
    const int tid = threadIdx.x, wid = tid >> 5, lane = tid & 31;
    const int e = blockIdx.x * 32 + wid * 4 + (lane >> 3);   // grid 25000 -> 800000 exactly
    const int j = lane & 7;
    const int src = g_ei[e], dst = g_ei[N_EDGES + e];
    const float2* av = reinterpret_cast<const float2*>(ea + (size_t)e * ED);
    const float2* pv = reinterpret_cast<const float2*>(g_p + (size_t)src * 56);
    float t = 0.f;
    #pragma unroll
    for (int r = 0; r < 4; r++) {
        int idx = j + r * 8;
        if (idx < 27) {
            float2 a = av[idx], p = pv[idx];
            t += a.x * p.x + a.y * p.y;
        }
    }
    if (j == 0) t += g_p[(size_t)src * 56 + 54];     // q term (implicit ea=1)
    t += __shfl_down_sync(0xffffffffu, t, 4, 8);
    t += __shfl_down_sync(0xffffffffu, t, 2, 8);
    t += __shfl_down_sync(0xffffffffu, t, 1, 8);
    if (j == 0) atomicAdd(out + dst, t);
}

// ---------------- launch ----------------
extern "C" void kernel_launch(void* const* d_in, const int* in_sizes, int n_in,
                              void* d_out, int out_size) {
    const float* x     = (const float*)d_in[0];
    const void*  ei    = d_in[1];
    const float* ea    = (const float*)d_in[2];
    const float* w_e1  = (const float*)d_in[3];
    const float* b_e1  = (const float*)d_in[4];
    const float* root1 = (const float*)d_in[5];
    const float* bias1 = (const float*)d_in[6];
    const float* w_e2  = (const float*)d_in[7];
    const float* b_e2  = (const float*)d_in[8];
    const float* root2 = (const float*)d_in[9];
    const float* bias2 = (const float*)d_in[10];
    float* out = (float*)d_out;

    k0a_detect<<<1, 32>>>((const int*)ei);
    k0b_convert_zero<<<6250, 256>>>(ei, w_e1, b_e1);
    k1_mma<<<N_EDGES / 128, 256>>>(x, ea);
    k2_node<<<N_NODES / 16, 256>>>(x, root1, bias1, w_e2, b_e2, root2, bias2, out);
    k3_edge_layer2<<<N_EDGES / 32, 256>>>(ea, out);
}

// round 13
// speedup vs baseline: 1.7516x; 1.2285x over previous
#include <cuda_runtime.h>
#include <cstdint>

#define N_NODES 50000
#define N_EDGES 800000
#define ED 54
#define HID 64

// ---------------- scratch (device globals: allocation-free rule) ----------------
__device__ float    g_agg[N_NODES * HID];   // layer-1 aggregation, 12.8 MB
__device__ float    g_p[N_NODES * 56];      // p[0..53], q at [54], pad to 56
__device__ int      g_ei[2 * N_EDGES];      // normalized int32 indices
__device__ uint2    g_w1[4 * 1792];         // tf32 B-frag pairs, [slice][(n*7+kb)*32 + g*4+tg]
__device__ int      g_idx_is64;             // dtype flag

__device__ __forceinline__ uint32_t f2tf32(float f) {
    uint32_t r;
    asm("cvt.rna.tf32.f32 %0, %1;" : "=r"(r) : "f"(f));
    return r;
}

// ---------------- K0a: detect edge_index dtype ----------------
__global__ void k0a_detect(const int* __restrict__ ei_raw) {
    int lane = threadIdx.x;
    int nz = 0;
    #pragma unroll
    for (int r = 0; r < 2; r++) {
        int i = lane + r * 32;
        if (ei_raw[(2 * i * 9973 % (2 * N_EDGES)) | 1] != 0) nz = 1;
    }
    #pragma unroll
    for (int off = 16; off; off >>= 1) nz |= __shfl_down_sync(0xffffffffu, nz, off);
    if (lane == 0) g_idx_is64 = (nz == 0);
}

// ---------------- K0b: normalize indices + zero g_agg + pack w_e1 tf32 frag-pairs ----------------
// Frag-pair layout (per slice): idx = (n*7 + kb)*32 + g*4 + tg
//   pair = { tf32(B[kb*8+tg][col]), tf32(B[kb*8+tg+4][col]) }, col = n*8+g
//   B[k][c] = w_e1[k*256 + sl*64 + c] (k<54) | b_e1[sl*64+c] (k==54) | 0
// Lane-varying part g*4+tg is a bijection onto 0..31 -> conflict-free LDS.64 in K1.
__global__ void k0b_convert_zero(const void* __restrict__ ei_raw,
                                 const float* __restrict__ w_e1,
                                 const float* __restrict__ b_e1) {
    int i = blockIdx.x * blockDim.x + threadIdx.x;   // 6250*256 = 1.6M exactly
    long long v;
    if (g_idx_is64) v = ((const long long*)ei_raw)[i];
    else            v = ((const int*)ei_raw)[i];
    if (v < 0) v = 0;
    if (v >= N_NODES) v = N_NODES - 1;
    g_ei[i] = (int)v;
    if (i < 800000) {                                 // 800000 float4s = 12.8MB
        float4 z = {0.f, 0.f, 0.f, 0.f};
        reinterpret_cast<float4*>(g_agg)[i] = z;
    }
    if (i < 4 * 1792) {                               // tf32 B-frag pair prep
        int sl = i / 1792, r = i - sl * 1792;
        int t = r >> 5, b = r & 31;
        int n = t / 7, kb = t - n * 7;
        int g = b >> 2, tg = b & 3;
        int k0 = kb * 8 + tg, k1 = k0 + 4;
        int c = sl * 64 + n * 8 + g;
        float w0 = (k0 < 54) ? w_e1[k0 * 256 + c] : ((k0 == 54) ? b_e1[c] : 0.f);
        float w1 = (k1 < 54) ? w_e1[k1 * 256 + c] : ((k1 == 54) ? b_e1[c] : 0.f);
        uint2 val; val.x = f2tf32(w0); val.y = f2tf32(w1);
        g_w1[i] = val;
    }
}

// ---------------- K1: layer-1 edge GEMM via mma.sync tf32 + scatter ----------------
// Per 128-edge tile: msgs[e,o] = sum_i x_i[e] * (A_raw[e,:] @ B_i[:,o])
//   A_raw held in REGISTERS (28 scalars/thread; k=54 -> 1.0, k=55 -> 0)
//   B_i frag-pairs copied from pre-packed g_w1 into smem per slice (uint2, conflict-free).
// 8 warps, warp owns m=16 edges x n=64 cols; K=56 per slice = 7 k8-steps.
__global__ __launch_bounds__(256, 3) void k1_mma(
    const float* __restrict__ x, const float* __restrict__ ea)
{
    __shared__ uint2 sB[1792];   // 14336 B: [(n*7+kb)*32 + g*4 + tg]

    const int tid  = threadIdx.x;
    const int wid  = tid >> 5;
    const int lane = tid & 31;
    const int g    = lane >> 2;     // 0..7
    const int tg   = lane & 3;      // 0..3
    const int wb   = wid * 16;      // warp's edge base within tile
    const int e0   = blockIdx.x * 128;        // 6250*128 = 800000

    // ---- per-thread edge metadata (2 edge rows: eA = wb+g, eB = wb+g+8) ----
    const int eA = e0 + wb + g, eB = e0 + wb + g + 8;
    const int srcA = g_ei[eA],          srcB = g_ei[eB];
    const int dstA = g_ei[N_EDGES + eA], dstB = g_ei[N_EDGES + eB];
    float4 xva = *reinterpret_cast<const float4*>(x + (size_t)srcA * 4);
    float4 xvb = *reinterpret_cast<const float4*>(x + (size_t)srcB * 4);
    float xA[4] = {xva.x, xva.y, xva.z, xva.w};
    float xB[4] = {xvb.x, xvb.y, xvb.z, xvb.w};

    // ---- raw A in registers: cols c1 = 8j+tg, c2 = 8j+tg+4 (j=0..6) ----
    const float* eaA = ea + (size_t)eA * ED;
    const float* eaB = ea + (size_t)eB * ED;
    float rA1[7], rA2[7], rB1[7], rB2[7];
    #pragma unroll
    for (int j = 0; j < 7; j++) { rA1[j] = eaA[8 * j + tg]; rB1[j] = eaB[8 * j + tg]; }
    #pragma unroll
    for (int j = 0; j < 6; j++) { rA2[j] = eaA[8 * j + tg + 4]; rB2[j] = eaB[8 * j + tg + 4]; }
    {   // j=6: col = 52+tg -> ea[52],ea[53], bias(1.0) at 54, pad(0) at 55
        if (tg < 2)      { rA2[6] = eaA[52 + tg]; rB2[6] = eaB[52 + tg]; }
        else if (tg == 2){ rA2[6] = 1.0f;         rB2[6] = 1.0f; }
        else             { rA2[6] = 0.0f;         rB2[6] = 0.0f; }
    }

    float acc[8][4];
    #pragma unroll
    for (int n = 0; n < 8; n++)
        #pragma unroll
        for (int c = 0; c < 4; c++) acc[n][c] = 0.f;

    #pragma unroll
    for (int i = 0; i < 4; i++) {
        __syncthreads();   // prior slice's mma reads of sB complete
        // ---- stage B slice i: linear uint2 copy from pre-packed global ----
        #pragma unroll
        for (int it = 0; it < 7; it++)                  // 7*256 = 1792 exactly
            sB[it * 256 + tid] = g_w1[i * 1792 + it * 256 + tid];
        __syncthreads();

        const float xa = xA[i], xb = xB[i];

        #pragma unroll
        for (int kb = 0; kb < 7; kb++) {
            uint32_t a0 = f2tf32(rA1[kb] * xa);
            uint32_t a1 = f2tf32(rB1[kb] * xb);
            uint32_t a2 = f2tf32(rA2[kb] * xa);
            uint32_t a3 = f2tf32(rB2[kb] * xb);
            const uint2* bp = sB + kb * 32 + g * 4 + tg;
            #pragma unroll
            for (int n = 0; n < 8; n++) {
                uint2 b = bp[n * 224];               // (n*7+kb)*32 + g*4+tg
                asm volatile(
                    "mma.sync.aligned.m16n8k8.row.col.f32.tf32.tf32.f32 "
                    "{%0,%1,%2,%3}, {%4,%5,%6,%7}, {%8,%9}, {%0,%1,%2,%3};"
                    : "+f"(acc[n][0]), "+f"(acc[n][1]), "+f"(acc[n][2]), "+f"(acc[n][3])
                    : "r"(a0), "r"(a1), "r"(a2), "r"(a3), "r"(b.x), "r"(b.y));
            }
        }
    }

    // ---- epilogue: c0,c1 -> edge eA; c2,c3 -> edge eB; cols tg*2 + n*8 ----
    float* pA = g_agg + (size_t)dstA * HID + tg * 2;
    float* pB = g_agg + (size_t)dstB * HID + tg * 2;
    #pragma unroll
    for (int n = 0; n < 8; n++) {
        asm volatile("red.global.add.v2.f32 [%0], {%1,%2};"
                     :: "l"(pA + n * 8), "f"(acc[n][0]), "f"(acc[n][1]) : "memory");
        asm volatile("red.global.add.v2.f32 [%0], {%1,%2};"
                     :: "l"(pB + n * 8), "f"(acc[n][2]), "f"(acc[n][3]) : "memory");
    }
}

// ---------------- K2: node update, 2 nodes per warp ----------------
__global__ __launch_bounds__(256) void k2_node(
    const float* __restrict__ x, const float* __restrict__ root1,
    const float* __restrict__ bias1, const float* __restrict__ w_e2,
    const float* __restrict__ b_e2, const float* __restrict__ root2,
    const float* __restrict__ bias2, float* __restrict__ out)
{
    __shared__ float sR1[256], sB1[64], sR2[64];
    __shared__ float sW2[55 * 65];      // row 54 = b_e2; stride 65 -> conflict-free
    __shared__ float sH[16][64];

    const int tid = threadIdx.x;
    for (int idx = tid; idx < 55 * 64; idx += 256) {
        int k = idx >> 6, o = idx & 63;
        sW2[k * 65 + o] = (k < 54) ? w_e2[k * 64 + o] : b_e2[o];
    }
    if (tid < 256) sR1[tid] = root1[tid];
    if (tid < 64) { sB1[tid] = bias1[tid]; sR2[tid] = root2[tid]; }
    __syncthreads();

    const int wid = tid >> 5, lane = tid & 31;
    const int n1 = blockIdx.x * 16 + wid * 2;        // grid 3125 -> exactly 50000 nodes
    const int n2 = n1 + 1;
    const int l2 = lane + 32;

    const float* ag1 = g_agg + (size_t)n1 * HID;
    const float* ag2 = g_agg + (size_t)n2 * HID;
    float4 xv1 = *reinterpret_cast<const float4*>(x + (size_t)n1 * 4);
    float4 xv2 = *reinterpret_cast<const float4*>(x + (size_t)n2 * 4);

    float h1a = ag1[lane] + xv1.x * sR1[lane] + xv1.y * sR1[64 + lane]
              + xv1.z * sR1[128 + lane] + xv1.w * sR1[192 + lane] + sB1[lane];
    float h1b = ag1[l2] + xv1.x * sR1[l2] + xv1.y * sR1[64 + l2]
              + xv1.z * sR1[128 + l2] + xv1.w * sR1[192 + l2] + sB1[l2];
    float h2a = ag2[lane] + xv2.x * sR1[lane] + xv2.y * sR1[64 + lane]
              + xv2.z * sR1[128 + lane] + xv2.w * sR1[192 + lane] + sB1[lane];
    float h2b = ag2[l2] + xv2.x * sR1[l2] + xv2.y * sR1[64 + l2]
              + xv2.z * sR1[128 + l2] + xv2.w * sR1[192 + l2] + sB1[l2];
    h1a = fmaxf(h1a, 0.f); h1b = fmaxf(h1b, 0.f);
    h2a = fmaxf(h2a, 0.f); h2b = fmaxf(h2b, 0.f);
    sH[wid * 2][lane] = h1a; sH[wid * 2][l2] = h1b;
    sH[wid * 2 + 1][lane] = h2a; sH[wid * 2 + 1][l2] = h2b;
    __syncwarp();

    const float* hr1 = sH[wid * 2];
    const float* hr2 = sH[wid * 2 + 1];
    float* p1 = g_p + (size_t)n1 * 56;
    float* p2 = g_p + (size_t)n2 * 56;
    {
        float a1 = 0.f, a2 = 0.f;
        #pragma unroll
        for (int o = 0; o < 64; o++) {
            float w = sW2[lane * 65 + o];
            a1 += w * hr1[o]; a2 += w * hr2[o];
        }
        p1[lane] = a1; p2[lane] = a2;
    }
    if (l2 < 55) {
        float a1 = 0.f, a2 = 0.f;
        #pragma unroll
        for (int o = 0; o < 64; o++) {
            float w = sW2[l2 * 65 + o];
            a1 += w * hr1[o]; a2 += w * hr2[o];
        }
        p1[l2] = a1; p2[l2] = a2;
    }
    // out init = h @ root2 + bias2
    float t1 = h1a * sR2[lane] + h1b * sR2[l2];
    float t2 = h2a * sR2[lane] + h2b * sR2[l2];
    #pragma unroll
    for (int off = 16; off; off >>= 1) {
        t1 += __shfl_down_sync(0xffffffffu, t1, off);
        t2 += __shfl_down_sync(0xffffffffu, t2, off);
    }
    if (lane == 0) { out[n1] = t1 + bias2[0]; out[n2] = t2 + bias2[0]; }
}

// ---------------- K3: layer-2 edges, 4 edges per warp (8 lanes each) ----------------
__global__ __launch_bounds__(256) void k3_edge_layer2(
    const float* __restrict__ ea, float* __restrict__ out)
{
    const int tid = threadIdx.x, wid = tid >> 5, lane = tid & 31;
    const int e = blockIdx.x * 32 + wid * 4 + (lane >> 3);   // grid 25000 -> 800000 exactly
    const int j = lane & 7;
    const int src = g_ei[e], dst = g_ei[N_EDGES + e];
    const float2* av = reinterpret_cast<const float2*>(ea + (size_t)e * ED);
    const float2* pv = reinterpret_cast<const float2*>(g_p + (size_t)src * 56);
    float t = 0.f;
    #pragma unroll
    for (int r = 0; r < 4; r++) {
        int idx = j + r * 8;
        if (idx < 27) {
            float2 a = av[idx], p = pv[idx];
            t += a.x * p.x + a.y * p.y;
        }
    }
    if (j == 0) t += g_p[(size_t)src * 56 + 54];     // q term (implicit ea=1)
    t += __shfl_down_sync(0xffffffffu, t, 4, 8);
    t += __shfl_down_sync(0xffffffffu, t, 2, 8);
    t += __shfl_down_sync(0xffffffffu, t, 1, 8);
    if (j == 0) atomicAdd(out + dst, t);
}

// ---------------- launch ----------------
extern "C" void kernel_launch(void* const* d_in, const int* in_sizes, int n_in,
                              void* d_out, int out_size) {
    const float* x     = (const float*)d_in[0];
    const void*  ei    = d_in[1];
    const float* ea    = (const float*)d_in[2];
    const float* w_e1  = (const float*)d_in[3];
    const float* b_e1  = (const float*)d_in[4];
    const float* root1 = (const float*)d_in[5];
    const float* bias1 = (const float*)d_in[6];
    const float* w_e2  = (const float*)d_in[7];
    const float* b_e2  = (const float*)d_in[8];
    const float* root2 = (const float*)d_in[9];
    const float* bias2 = (const float*)d_in[10];
    float* out = (float*)d_out;

    k0a_detect<<<1, 32>>>((const int*)ei);
    k0b_convert_zero<<<6250, 256>>>(ei, w_e1, b_e1);
    k1_mma<<<N_EDGES / 128, 256>>>(x, ea);
    k2_node<<<N_NODES / 16, 256>>>(x, root1, bias1, w_e2, b_e2, root2, bias2, out);
    k3_edge_layer2<<<N_EDGES / 32, 256>>>(ea, out);
}

// round 14
// speedup vs baseline: 1.8607x; 1.0623x over previous
#include <cuda_runtime.h>
#include <cstdint>

#define N_NODES 50000
#define N_EDGES 800000
#define ED 54
#define HID 64

// ---------------- scratch (device globals: allocation-free rule) ----------------
__device__ float    g_agg[N_NODES * HID];   // layer-1 aggregation, 12.8 MB
__device__ float    g_p[N_NODES * 56];      // p[0..53], q at [54], pad to 56
__device__ int      g_ei[2 * N_EDGES];      // normalized int32 indices
__device__ uint2    g_w1[4 * 1792];         // tf32 B-frag pairs, [slice][(n*7+kb)*32 + g*4+tg]
__device__ int      g_idx_is64;             // dtype flag

__device__ __forceinline__ uint32_t f2tf32(float f) {
    uint32_t r;
    asm("cvt.rna.tf32.f32 %0, %1;" : "=r"(r) : "f"(f));
    return r;
}

// ---------------- K0a: detect edge_index dtype ----------------
__global__ void k0a_detect(const int* __restrict__ ei_raw) {
    int lane = threadIdx.x;
    int nz = 0;
    #pragma unroll
    for (int r = 0; r < 2; r++) {
        int i = lane + r * 32;
        if (ei_raw[(2 * i * 9973 % (2 * N_EDGES)) | 1] != 0) nz = 1;
    }
    #pragma unroll
    for (int off = 16; off; off >>= 1) nz |= __shfl_down_sync(0xffffffffu, nz, off);
    if (lane == 0) g_idx_is64 = (nz == 0);
}

// ---------------- K0b: normalize indices + zero g_agg + pack w_e1 tf32 frag-pairs ----------------
// Frag-pair layout (per slice): idx = (n*7 + kb)*32 + g*4 + tg
//   pair = { tf32(B[kb*8+tg][col]), tf32(B[kb*8+tg+4][col]) }, col = n*8+g
//   B[k][c] = w_e1[k*256 + sl*64 + c] (k<54) | b_e1[sl*64+c] (k==54) | 0
// Lane-varying part g*4+tg is a bijection onto 0..31 -> conflict-free LDS.64 in K1.
__global__ void k0b_convert_zero(const void* __restrict__ ei_raw,
                                 const float* __restrict__ w_e1,
                                 const float* __restrict__ b_e1) {
    int i = blockIdx.x * blockDim.x + threadIdx.x;   // 6250*256 = 1.6M exactly
    long long v;
    if (g_idx_is64) v = ((const long long*)ei_raw)[i];
    else            v = ((const int*)ei_raw)[i];
    if (v < 0) v = 0;
    if (v >= N_NODES) v = N_NODES - 1;
    g_ei[i] = (int)v;
    if (i < 800000) {                                 // 800000 float4s = 12.8MB
        float4 z = {0.f, 0.f, 0.f, 0.f};
        reinterpret_cast<float4*>(g_agg)[i] = z;
    }
    if (i < 4 * 1792) {                               // tf32 B-frag pair prep
        int sl = i / 1792, r = i - sl * 1792;
        int t = r >> 5, b = r & 31;
        int n = t / 7, kb = t - n * 7;
        int g = b >> 2, tg = b & 3;
        int k0 = kb * 8 + tg, k1 = k0 + 4;
        int c = sl * 64 + n * 8 + g;
        float w0 = (k0 < 54) ? w_e1[k0 * 256 + c] : ((k0 == 54) ? b_e1[c] : 0.f);
        float w1 = (k1 < 54) ? w_e1[k1 * 256 + c] : ((k1 == 54) ? b_e1[c] : 0.f);
        uint2 val; val.x = f2tf32(w0); val.y = f2tf32(w1);
        g_w1[i] = val;
    }
}

// ---------------- K1: layer-1 edge GEMM via mma.sync tf32 + scatter ----------------
// Per 128-edge tile: msgs[e,o] = sum_i x_i[e] * (A_raw[e,:] @ B_i[:,o])
//   A_raw held in REGISTERS (28 scalars/thread; k=54 -> 1.0, k=55 -> 0)
//   A-operands fed as RAW fp32 bits (tf32 truncation, CUTLASS no-round path) -> no inner CVT.
//   B_i frag-pairs copied from pre-packed g_w1 into smem per slice (uint2, conflict-free).
// 8 warps, warp owns m=16 edges x n=64 cols; K=56 per slice = 7 k8-steps.
__global__ __launch_bounds__(256, 3) void k1_mma(
    const float* __restrict__ x, const float* __restrict__ ea)
{
    __shared__ uint2 sB[1792];   // 14336 B: [(n*7+kb)*32 + g*4 + tg]

    const int tid  = threadIdx.x;
    const int wid  = tid >> 5;
    const int lane = tid & 31;
    const int g    = lane >> 2;     // 0..7
    const int tg   = lane & 3;      // 0..3
    const int wb   = wid * 16;      // warp's edge base within tile
    const int e0   = blockIdx.x * 128;        // 6250*128 = 800000

    // ---- per-thread edge metadata (2 edge rows: eA = wb+g, eB = wb+g+8) ----
    const int eA = e0 + wb + g, eB = e0 + wb + g + 8;
    const int srcA = g_ei[eA],          srcB = g_ei[eB];
    const int dstA = g_ei[N_EDGES + eA], dstB = g_ei[N_EDGES + eB];
    float4 xva = *reinterpret_cast<const float4*>(x + (size_t)srcA * 4);
    float4 xvb = *reinterpret_cast<const float4*>(x + (size_t)srcB * 4);
    float xA[4] = {xva.x, xva.y, xva.z, xva.w};
    float xB[4] = {xvb.x, xvb.y, xvb.z, xvb.w};

    // ---- raw A in registers: cols c1 = 8j+tg, c2 = 8j+tg+4 (j=0..6) ----
    const float* eaA = ea + (size_t)eA * ED;
    const float* eaB = ea + (size_t)eB * ED;
    float rA1[7], rA2[7], rB1[7], rB2[7];
    #pragma unroll
    for (int j = 0; j < 7; j++) { rA1[j] = eaA[8 * j + tg]; rB1[j] = eaB[8 * j + tg]; }
    #pragma unroll
    for (int j = 0; j < 6; j++) { rA2[j] = eaA[8 * j + tg + 4]; rB2[j] = eaB[8 * j + tg + 4]; }
    {   // j=6: col = 52+tg -> ea[52],ea[53], bias(1.0) at 54, pad(0) at 55
        if (tg < 2)      { rA2[6] = eaA[52 + tg]; rB2[6] = eaB[52 + tg]; }
        else if (tg == 2){ rA2[6] = 1.0f;         rB2[6] = 1.0f; }
        else             { rA2[6] = 0.0f;         rB2[6] = 0.0f; }
    }

    float acc[8][4];
    #pragma unroll
    for (int n = 0; n < 8; n++)
        #pragma unroll
        for (int c = 0; c < 4; c++) acc[n][c] = 0.f;

    #pragma unroll
    for (int i = 0; i < 4; i++) {
        __syncthreads();   // prior slice's mma reads of sB complete
        // ---- stage B slice i: linear uint2 copy from pre-packed global ----
        #pragma unroll
        for (int it = 0; it < 7; it++)                  // 7*256 = 1792 exactly
            sB[it * 256 + tid] = g_w1[i * 1792 + it * 256 + tid];
        __syncthreads();

        const float xa = xA[i], xb = xB[i];

        #pragma unroll
        for (int kb = 0; kb < 7; kb++) {
            uint32_t a0 = __float_as_uint(rA1[kb] * xa);   // raw bits = tf32 truncation
            uint32_t a1 = __float_as_uint(rB1[kb] * xb);
            uint32_t a2 = __float_as_uint(rA2[kb] * xa);
            uint32_t a3 = __float_as_uint(rB2[kb] * xb);
            const uint2* bp = sB + kb * 32 + g * 4 + tg;
            #pragma unroll
            for (int n = 0; n < 8; n++) {
                uint2 b = bp[n * 224];               // (n*7+kb)*32 + g*4+tg
                asm volatile(
                    "mma.sync.aligned.m16n8k8.row.col.f32.tf32.tf32.f32 "
                    "{%0,%1,%2,%3}, {%4,%5,%6,%7}, {%8,%9}, {%0,%1,%2,%3};"
                    : "+f"(acc[n][0]), "+f"(acc[n][1]), "+f"(acc[n][2]), "+f"(acc[n][3])
                    : "r"(a0), "r"(a1), "r"(a2), "r"(a3), "r"(b.x), "r"(b.y));
            }
        }
    }

    // ---- epilogue: c0,c1 -> edge eA; c2,c3 -> edge eB; cols tg*2 + n*8 ----
    float* pA = g_agg + (size_t)dstA * HID + tg * 2;
    float* pB = g_agg + (size_t)dstB * HID + tg * 2;
    #pragma unroll
    for (int n = 0; n < 8; n++) {
        asm volatile("red.global.add.v2.f32 [%0], {%1,%2};"
                     :: "l"(pA + n * 8), "f"(acc[n][0]), "f"(acc[n][1]) : "memory");
        asm volatile("red.global.add.v2.f32 [%0], {%1,%2};"
                     :: "l"(pB + n * 8), "f"(acc[n][2]), "f"(acc[n][3]) : "memory");
    }
}

// ---------------- K2: node update, 64 nodes/CTA (warp loops 4x over 2-node body) ----------------
__global__ __launch_bounds__(256) void k2_node(
    const float* __restrict__ x, const float* __restrict__ root1,
    const float* __restrict__ bias1, const float* __restrict__ w_e2,
    const float* __restrict__ b_e2, const float* __restrict__ root2,
    const float* __restrict__ bias2, float* __restrict__ out)
{
    __shared__ float sR1[256], sB1[64], sR2[64];
    __shared__ float sW2[55 * 65];      // row 54 = b_e2; stride 65 -> conflict-free
    __shared__ float sH[16][64];

    const int tid = threadIdx.x;
    for (int idx = tid; idx < 55 * 64; idx += 256) {
        int k = idx >> 6, o = idx & 63;
        sW2[k * 65 + o] = (k < 54) ? w_e2[k * 64 + o] : b_e2[o];
    }
    if (tid < 256) sR1[tid] = root1[tid];
    if (tid < 64) { sB1[tid] = bias1[tid]; sR2[tid] = root2[tid]; }
    __syncthreads();

    const int wid = tid >> 5, lane = tid & 31;
    const int l2 = lane + 32;
    const float b2 = bias2[0];

    #pragma unroll
    for (int it = 0; it < 4; it++) {
        const int n1 = blockIdx.x * 64 + wid * 8 + it * 2;   // grid 782 covers 50048
        if (n1 >= N_NODES) break;                            // N_NODES even -> pairs whole
        const int n2 = n1 + 1;

        const float* ag1 = g_agg + (size_t)n1 * HID;
        const float* ag2 = g_agg + (size_t)n2 * HID;
        float4 xv1 = *reinterpret_cast<const float4*>(x + (size_t)n1 * 4);
        float4 xv2 = *reinterpret_cast<const float4*>(x + (size_t)n2 * 4);

        float h1a = ag1[lane] + xv1.x * sR1[lane] + xv1.y * sR1[64 + lane]
                  + xv1.z * sR1[128 + lane] + xv1.w * sR1[192 + lane] + sB1[lane];
        float h1b = ag1[l2] + xv1.x * sR1[l2] + xv1.y * sR1[64 + l2]
                  + xv1.z * sR1[128 + l2] + xv1.w * sR1[192 + l2] + sB1[l2];
        float h2a = ag2[lane] + xv2.x * sR1[lane] + xv2.y * sR1[64 + lane]
                  + xv2.z * sR1[128 + lane] + xv2.w * sR1[192 + lane] + sB1[lane];
        float h2b = ag2[l2] + xv2.x * sR1[l2] + xv2.y * sR1[64 + l2]
                  + xv2.z * sR1[128 + l2] + xv2.w * sR1[192 + l2] + sB1[l2];
        h1a = fmaxf(h1a, 0.f); h1b = fmaxf(h1b, 0.f);
        h2a = fmaxf(h2a, 0.f); h2b = fmaxf(h2b, 0.f);
        sH[wid * 2][lane] = h1a; sH[wid * 2][l2] = h1b;
        sH[wid * 2 + 1][lane] = h2a; sH[wid * 2 + 1][l2] = h2b;
        __syncwarp();

        const float* hr1 = sH[wid * 2];
        const float* hr2 = sH[wid * 2 + 1];
        float* p1 = g_p + (size_t)n1 * 56;
        float* p2 = g_p + (size_t)n2 * 56;
        {
            float a1 = 0.f, a2 = 0.f;
            #pragma unroll
            for (int o = 0; o < 64; o++) {
                float w = sW2[lane * 65 + o];
                a1 += w * hr1[o]; a2 += w * hr2[o];
            }
            p1[lane] = a1; p2[lane] = a2;
        }
        if (l2 < 55) {
            float a1 = 0.f, a2 = 0.f;
            #pragma unroll
            for (int o = 0; o < 64; o++) {
                float w = sW2[l2 * 65 + o];
                a1 += w * hr1[o]; a2 += w * hr2[o];
            }
            p1[l2] = a1; p2[l2] = a2;
        }
        // out init = h @ root2 + bias2
        float t1 = h1a * sR2[lane] + h1b * sR2[l2];
        float t2 = h2a * sR2[lane] + h2b * sR2[l2];
        #pragma unroll
        for (int off = 16; off; off >>= 1) {
            t1 += __shfl_down_sync(0xffffffffu, t1, off);
            t2 += __shfl_down_sync(0xffffffffu, t2, off);
        }
        if (lane == 0) { out[n1] = t1 + b2; out[n2] = t2 + b2; }
        __syncwarp();
    }
}

// ---------------- K3: layer-2 edges, 4 edges per warp (8 lanes each) ----------------
__global__ __launch_bounds__(256) void k3_edge_layer2(
    const float* __restrict__ ea, float* __restrict__ out)
{
    const int tid = threadIdx.x, wid = tid >> 5, lane = tid & 31;
    const int e = blockIdx.x * 32 + wid * 4 + (lane >> 3);   // grid 25000 -> 800000 exactly
    const int j = lane & 7;
    const int src = g_ei[e], dst = g_ei[N_EDGES + e];
    const float2* av = reinterpret_cast<const float2*>(ea + (size_t)e * ED);
    const float2* pv = reinterpret_cast<const float2*>(g_p + (size_t)src * 56);
    float t = 0.f;
    #pragma unroll
    for (int r = 0; r < 4; r++) {
        int idx = j + r * 8;
        if (idx < 27) {
            float2 a = av[idx], p = pv[idx];
            t += a.x * p.x + a.y * p.y;
        }
    }
    if (j == 0) t += g_p[(size_t)src * 56 + 54];     // q term (implicit ea=1)
    t += __shfl_down_sync(0xffffffffu, t, 4, 8);
    t += __shfl_down_sync(0xffffffffu, t, 2, 8);
    t += __shfl_down_sync(0xffffffffu, t, 1, 8);
    if (j == 0) atomicAdd(out + dst, t);
}

// ---------------- launch ----------------
extern "C" void kernel_launch(void* const* d_in, const int* in_sizes, int n_in,
                              void* d_out, int out_size) {
    const float* x     = (const float*)d_in[0];
    const void*  ei    = d_in[1];
    const float* ea    = (const float*)d_in[2];
    const float* w_e1  = (const float*)d_in[3];
    const float* b_e1  = (const float*)d_in[4];
    const float* root1 = (const float*)d_in[5];
    const float* bias1 = (const float*)d_in[6];
    const float* w_e2  = (const float*)d_in[7];
    const float* b_e2  = (const float*)d_in[8];
    const float* root2 = (const float*)d_in[9];
    const float* bias2 = (const float*)d_in[10];
    float* out = (float*)d_out;

    k0a_detect<<<1, 32>>>((const int*)ei);
    k0b_convert_zero<<<6250, 256>>>(ei, w_e1, b_e1);
    k1_mma<<<N_EDGES / 128, 256>>>(x, ea);
    k2_node<<<(N_NODES + 63) / 64, 256>>>(x, root1, bias1, w_e2, b_e2, root2, bias2, out);
    k3_edge_layer2<<<N_EDGES / 32, 256>>>(ea, out);
}